// round 11
// baseline (speedup 1.0000x reference)
#include <cuda_runtime.h>
#include <cstdint>

#define E_TOTAL   800000
#define D_IN      64
#define D_R       128
#define TILE_E    128
#define NTHREADS  512
#define GRID      148
#define NUM_TILES (E_TOTAL / TILE_E)  // 6250, exact
#define A_STRIDE  132                 // padded fp32 row stride (528B)
#define C_STRIDE  68                  // padded filt stride (272B)
#define GROUP_E   32                  // edges per 128-thread group
#define SCALE_FIX 1.000352f           // cancels tf32 truncation bias on A

struct Group {
    float A[2][GROUP_E * A_STRIDE];   // 2 x 16.9 KB (double-buffered)
    float filt[2][GROUP_E * C_STRIDE];// 2 planes (deferred scatter), 2 x 8.7 KB
};
struct Smem { Group gr[4]; };         // ~205 KB

// ---------------- helpers ----------------
__device__ __forceinline__ uint32_t smem_u32(const void* p) {
    uint32_t a;
    asm("{ .reg .u64 t; cvta.to.shared.u64 t, %1; cvt.u32.u64 %0, t; }" : "=r"(a) : "l"(p));
    return a;
}
__device__ __forceinline__ void cp_async16(uint32_t saddr, const void* gptr) {
    asm volatile("cp.async.cg.shared.global [%0], [%1], 16;" :: "r"(saddr), "l"(gptr));
}
#define CP_COMMIT() asm volatile("cp.async.commit_group;" ::: "memory")
#define CP_WAIT0()  asm volatile("cp.async.wait_group 0;" ::: "memory")
#define GBAR(id)    asm volatile("bar.sync %0, 128;" :: "r"(id) : "memory")

// ldmatrix x4 .b16 on an 8x8-f32-col-pair view: exact m16n8k8 tf32 A fragment.
__device__ __forceinline__ void ldsm_x4(uint32_t& r0, uint32_t& r1,
                                        uint32_t& r2, uint32_t& r3, uint32_t addr) {
    asm volatile("ldmatrix.sync.aligned.m8n8.x4.shared.b16 {%0,%1,%2,%3}, [%4];"
                 : "=r"(r0), "=r"(r1), "=r"(r2), "=r"(r3) : "r"(addr));
}

__device__ __forceinline__ void mma_tf32(float c[4],
                                         uint32_t a0, uint32_t a1, uint32_t a2, uint32_t a3,
                                         uint32_t b0, uint32_t b1) {
    asm volatile(
        "mma.sync.aligned.m16n8k8.row.col.f32.tf32.tf32.f32 "
        "{%0,%1,%2,%3}, {%4,%5,%6,%7}, {%8,%9}, {%0,%1,%2,%3};"
        : "+f"(c[0]), "+f"(c[1]), "+f"(c[2]), "+f"(c[3])
        : "r"(a0), "r"(a1), "r"(a2), "r"(a3), "r"(b0), "r"(b1));
}
__device__ __forceinline__ uint32_t f2tf32_rna(float f) {
    uint32_t r;
    asm("cvt.rna.tf32.f32 %0, %1;" : "=r"(r) : "f"(f));
    return r;
}
__device__ __forceinline__ void red_add_v4(float* p, float a, float b, float c, float d) {
    asm volatile("red.global.add.v4.f32 [%0], {%1, %2, %3, %4};"
                 :: "l"(p), "f"(a), "f"(b), "f"(c), "f"(d) : "memory");
}

__global__ void zero_out_kernel(float4* out, int n4) {
    int i = blockIdx.x * blockDim.x + threadIdx.x;
    if (i < n4) out[i] = make_float4(0.f, 0.f, 0.f, 0.f);
}

// Group loads its own 32 rows of tile tl: exactly 8 float4s per thread.
__device__ __forceinline__ void issue_group_tile(float* abuf, int tl, int grp, int tid_g,
                                                 const float* __restrict__ eb) {
    const float4* gp = reinterpret_cast<const float4*>(
        eb + ((size_t)tl * TILE_E + grp * GROUP_E) * D_R);
    #pragma unroll
    for (int q = 0; q < 8; q++) {
        int idx = q * 128 + tid_g;          // 0..1023
        int r   = idx >> 5;                 // local row 0..31
        int c4  = idx & 31;
        cp_async16(smem_u32(abuf + r * A_STRIDE + c4 * 4), gp + idx);
    }
}

// ---------------- main fused kernel ----------------
__global__ void __launch_bounds__(NTHREADS, 1)
fused_tf32_defer(const float* __restrict__ x,
                 const float* __restrict__ eb,
                 const int*   __restrict__ src,
                 const int*   __restrict__ dst,
                 const float* __restrict__ W,
                 const float* __restrict__ bias,
                 float*       __restrict__ out)
{
    extern __shared__ char smem_raw[];
    Smem* s = reinterpret_cast<Smem*>(smem_raw);

    const int tid   = threadIdx.x;
    const int lane  = tid & 31;
    const int g     = lane >> 2;      // 0..7
    const int t     = lane & 3;       // 0..3
    const int grp   = tid >> 7;       // 0..3
    const int tid_g = tid & 127;
    const int ng    = (tid >> 5) & 3; // warp-in-group = n group
    const int barid = 1 + grp;
    const int eL    = tid_g >> 4;     // scatter base edge (0..7)

    Group* G = &s->gr[grp];

    // ldmatrix per-lane offset (bytes) within an A buffer
    const int lrow = ((lane >> 3) & 1) * 8 + (lane & 7);
    const uint32_t laneoff = (uint32_t)(lrow * (A_STRIDE * 4) + (lane >> 4) * 16);
    const uint32_t abuf_addr[2] = { smem_u32(G->A[0]), smem_u32(G->A[1]) };

    // ---- W fragments resident in registers (64 regs/thread) ----
    float2 wreg[16][2];
    #pragma unroll
    for (int ks = 0; ks < 16; ks++) {
        #pragma unroll
        for (int j = 0; j < 2; j++) {
            int n = ng * 16 + j * 8 + g;
            int k = ks * 8 + t;
            wreg[ks][j].x = __uint_as_float(f2tf32_rna(__ldg(W + n * D_R + k)));
            wreg[ks][j].y = __uint_as_float(f2tf32_rna(__ldg(W + n * D_R + k + 4)));
        }
    }
    const int d4 = tid_g & 15;
    const float4 bvec = __ldg(reinterpret_cast<const float4*>(bias) + d4);

    const int bid     = blockIdx.x;
    const int n_tiles = (NUM_TILES - bid + GRID - 1) / GRID;

    // ---- prologue: prefetch tile 0 slice; preload tile 0 indices ----
    issue_group_tile(G->A[0], bid, grp, tid_g, eb);
    CP_COMMIT();

    int snP[4], dnP[4];   // indices of tile i-1's scatter edges (carried)
    {
        const int ebase0 = bid * TILE_E + grp * GROUP_E;
        #pragma unroll
        for (int r = 0; r < 4; r++) {
            snP[r] = __ldg(src + ebase0 + eL + 8 * r);
            dnP[r] = __ldg(dst + ebase0 + eL + 8 * r);
        }
    }

    for (int i = 0; i < n_tiles; i++) {
        CP_WAIT0();                 // this group's tile i slice resident
        GBAR(barid);                // publish A[i&1]; whole group finished
                                    // iter i-1 (incl. filt[(i-1)&1] staging
                                    // and scatter of tile i-2)

        // ---- prefetch tile i+1 slice ----
        if (i + 1 < n_tiles) {
            issue_group_tile(G->A[(i + 1) & 1], bid + (i + 1) * GRID, grp, tid_g, eb);
            CP_COMMIT();
        }

        // ---- early gather for tile i-1's scatter (indices already in regs) ----
        float4 xv[4];
        if (i > 0) {
            #pragma unroll
            for (int r = 0; r < 4; r++)
                xv[r] = __ldg(reinterpret_cast<const float4*>(
                                  x + (size_t)snP[r] * D_IN) + d4);
        }
        // ---- preload tile i's indices (used for scatter at iter i+1) ----
        int snC[4], dnC[4];
        {
            const int ebase = (bid + i * GRID) * TILE_E + grp * GROUP_E;
            #pragma unroll
            for (int r = 0; r < 4; r++) {
                snC[r] = __ldg(src + ebase + eL + 8 * r);
                dnC[r] = __ldg(dst + ebase + eL + 8 * r);
            }
        }

        // ---- MMA: warp = 32 edges x 16 n; gathers fly during this ----
        const uint32_t abase = abuf_addr[i & 1] + laneoff;
        float c[2][2][4];
        #pragma unroll
        for (int m = 0; m < 2; m++)
            #pragma unroll
            for (int j = 0; j < 2; j++)
                { c[m][j][0] = 0.f; c[m][j][1] = 0.f; c[m][j][2] = 0.f; c[m][j][3] = 0.f; }

        #pragma unroll
        for (int ks = 0; ks < 16; ks++) {
            #pragma unroll
            for (int m = 0; m < 2; m++) {
                uint32_t a0, a1, a2, a3;
                ldsm_x4(a0, a1, a2, a3,
                        abase + (uint32_t)(m * 16 * (A_STRIDE * 4) + ks * 32));
                #pragma unroll
                for (int j = 0; j < 2; j++)
                    mma_tf32(c[m][j], a0, a1, a2, a3,
                             __float_as_uint(wreg[ks][j].x),
                             __float_as_uint(wreg[ks][j].y));
            }
        }

        // ---- stage C of tile i into filt[i&1] (kills accumulators early) ----
        #pragma unroll
        for (int m = 0; m < 2; m++) {
            float* fr = G->filt[i & 1] + (m * 16 + g) * C_STRIDE + ng * 16;
            #pragma unroll
            for (int j = 0; j < 2; j++) {
                *reinterpret_cast<float2*>(fr + j * 8 + 2 * t) =
                    make_float2(c[m][j][0], c[m][j][1]);
                *reinterpret_cast<float2*>(fr + 8 * C_STRIDE + j * 8 + 2 * t) =
                    make_float2(c[m][j][2], c[m][j][3]);
            }
        }

        // ---- scatter tile i-1 from filt[(i-1)&1], xv already arrived ----
        if (i > 0) {
            const float* fp = G->filt[(i - 1) & 1];
            #pragma unroll
            for (int r = 0; r < 4; r++) {
                float4 f = *reinterpret_cast<const float4*>(
                               fp + (eL + 8 * r) * C_STRIDE + d4 * 4);
                red_add_v4(out + (size_t)dnP[r] * D_IN + d4 * 4,
                           fmaf(f.x, SCALE_FIX, bvec.x) * xv[r].x,
                           fmaf(f.y, SCALE_FIX, bvec.y) * xv[r].y,
                           fmaf(f.z, SCALE_FIX, bvec.z) * xv[r].z,
                           fmaf(f.w, SCALE_FIX, bvec.w) * xv[r].w);
            }
        }

        // ---- carry indices ----
        #pragma unroll
        for (int r = 0; r < 4; r++) { snP[r] = snC[r]; dnP[r] = dnC[r]; }
    }

    // ---- final scatter: tile n_tiles-1 ----
    GBAR(barid);                    // all warps staged filt[(n-1)&1]
    {
        const float* fp = G->filt[(n_tiles - 1) & 1];
        #pragma unroll
        for (int r = 0; r < 4; r++) {
            float4 xvf = __ldg(reinterpret_cast<const float4*>(
                                   x + (size_t)snP[r] * D_IN) + d4);
            float4 f = *reinterpret_cast<const float4*>(
                           fp + (eL + 8 * r) * C_STRIDE + d4 * 4);
            red_add_v4(out + (size_t)dnP[r] * D_IN + d4 * 4,
                       fmaf(f.x, SCALE_FIX, bvec.x) * xvf.x,
                       fmaf(f.y, SCALE_FIX, bvec.y) * xvf.y,
                       fmaf(f.z, SCALE_FIX, bvec.z) * xvf.z,
                       fmaf(f.w, SCALE_FIX, bvec.w) * xvf.w);
        }
    }
}

extern "C" void kernel_launch(void* const* d_in, const int* in_sizes, int n_in,
                              void* d_out, int out_size) {
    const float* x    = (const float*)d_in[0];
    const float* eb   = (const float*)d_in[1];
    const int*   src  = (const int*)d_in[2];
    const int*   dst  = (const int*)d_in[3];
    const float* W    = (const float*)d_in[4];
    const float* bias = (const float*)d_in[5];
    float* out = (float*)d_out;

    int n4 = out_size / 4;
    zero_out_kernel<<<(n4 + 255) / 256, 256>>>((float4*)out, n4);

    cudaFuncSetAttribute(fused_tf32_defer,
                         cudaFuncAttributeMaxDynamicSharedMemorySize,
                         (int)sizeof(Smem));
    fused_tf32_defer<<<GRID, NTHREADS, sizeof(Smem)>>>(x, eb, src, dst, W, bias, out);
}

// round 12
// speedup vs baseline: 1.0604x; 1.0604x over previous
#include <cuda_runtime.h>
#include <cstdint>

#define E_TOTAL   800000
#define D_IN      64
#define D_R       128
#define TILE_E    128
#define NTHREADS  512
#define GRID      148
#define NUM_TILES (E_TOTAL / TILE_E)  // 6250, exact
#define A_STRIDE  132                 // padded fp32 row stride (528B)
#define C_STRIDE  68                  // padded filt stride (272B)
#define XG_STRIDE 68                  // padded gather stride (272B)
#define GROUP_E   32                  // edges per 128-thread group
#define SCALE_FIX 1.000352f           // cancels tf32 truncation bias on A

struct Group {
    float A[2][GROUP_E * A_STRIDE];   // 2 x 16.9 KB (double-buffered)
    float filt[GROUP_E * C_STRIDE];   // 8.7 KB
    float xg[GROUP_E * XG_STRIDE];    // 8.7 KB gathered x rows (per tile)
    int   sidx[2][GROUP_E];           // double-buffered with A
    int   didx[2][GROUP_E];
};
struct Smem { Group gr[4]; };         // ~207 KB

// ---------------- helpers ----------------
__device__ __forceinline__ uint32_t smem_u32(const void* p) {
    uint32_t a;
    asm("{ .reg .u64 t; cvta.to.shared.u64 t, %1; cvt.u32.u64 %0, t; }" : "=r"(a) : "l"(p));
    return a;
}
__device__ __forceinline__ void cp_async16(uint32_t saddr, const void* gptr) {
    asm volatile("cp.async.cg.shared.global [%0], [%1], 16;" :: "r"(saddr), "l"(gptr));
}
#define CP_COMMIT() asm volatile("cp.async.commit_group;" ::: "memory")
#define CP_WAIT0()  asm volatile("cp.async.wait_group 0;" ::: "memory")
#define CP_WAIT1()  asm volatile("cp.async.wait_group 1;" ::: "memory")
#define GBAR(id)    asm volatile("bar.sync %0, 128;" :: "r"(id) : "memory")

// ldmatrix x4 .b16 on an 8x8-f32-col-pair view: exact m16n8k8 tf32 A fragment.
__device__ __forceinline__ void ldsm_x4(uint32_t& r0, uint32_t& r1,
                                        uint32_t& r2, uint32_t& r3, uint32_t addr) {
    asm volatile("ldmatrix.sync.aligned.m8n8.x4.shared.b16 {%0,%1,%2,%3}, [%4];"
                 : "=r"(r0), "=r"(r1), "=r"(r2), "=r"(r3) : "r"(addr));
}

__device__ __forceinline__ void mma_tf32(float c[4],
                                         uint32_t a0, uint32_t a1, uint32_t a2, uint32_t a3,
                                         uint32_t b0, uint32_t b1) {
    asm volatile(
        "mma.sync.aligned.m16n8k8.row.col.f32.tf32.tf32.f32 "
        "{%0,%1,%2,%3}, {%4,%5,%6,%7}, {%8,%9}, {%0,%1,%2,%3};"
        : "+f"(c[0]), "+f"(c[1]), "+f"(c[2]), "+f"(c[3])
        : "r"(a0), "r"(a1), "r"(a2), "r"(a3), "r"(b0), "r"(b1));
}
__device__ __forceinline__ uint32_t f2tf32_rna(float f) {
    uint32_t r;
    asm("cvt.rna.tf32.f32 %0, %1;" : "=r"(r) : "f"(f));
    return r;
}
__device__ __forceinline__ void red_add_v4(float* p, float a, float b, float c, float d) {
    asm volatile("red.global.add.v4.f32 [%0], {%1, %2, %3, %4};"
                 :: "l"(p), "f"(a), "f"(b), "f"(c), "f"(d) : "memory");
}

__global__ void zero_out_kernel(float4* out, int n4) {
    int i = blockIdx.x * blockDim.x + threadIdx.x;
    if (i < n4) out[i] = make_float4(0.f, 0.f, 0.f, 0.f);
}

// Group loads its own 32 rows of tile tl (8 float4s/thread) + the tile's
// src/dst indices (bundled into the same commit group).
__device__ __forceinline__ void issue_group_tile(Group* G, int buf, int tl, int grp,
                                                 int tid_g,
                                                 const float* __restrict__ eb,
                                                 const int* __restrict__ src,
                                                 const int* __restrict__ dst) {
    const float4* gp = reinterpret_cast<const float4*>(
        eb + ((size_t)tl * TILE_E + grp * GROUP_E) * D_R);
    float* abuf = G->A[buf];
    #pragma unroll
    for (int q = 0; q < 8; q++) {
        int idx = q * 128 + tid_g;          // 0..1023
        int r   = idx >> 5;                 // local row 0..31
        int c4  = idx & 31;
        cp_async16(smem_u32(abuf + r * A_STRIDE + c4 * 4), gp + idx);
    }
    const int ebase = tl * TILE_E + grp * GROUP_E;
    if (tid_g < 8)
        cp_async16(smem_u32(&G->sidx[buf][tid_g * 4]), src + ebase + tid_g * 4);
    else if (tid_g < 16)
        cp_async16(smem_u32(&G->didx[buf][(tid_g - 8) * 4]), dst + ebase + (tid_g - 8) * 4);
}

// ---------------- main fused kernel ----------------
__global__ void __launch_bounds__(NTHREADS, 1)
fused_tf32_xg(const float* __restrict__ x,
              const float* __restrict__ eb,
              const int*   __restrict__ src,
              const int*   __restrict__ dst,
              const float* __restrict__ W,
              const float* __restrict__ bias,
              float*       __restrict__ out)
{
    extern __shared__ char smem_raw[];
    Smem* s = reinterpret_cast<Smem*>(smem_raw);

    const int tid   = threadIdx.x;
    const int lane  = tid & 31;
    const int g     = lane >> 2;      // 0..7
    const int t     = lane & 3;       // 0..3
    const int grp   = tid >> 7;       // 0..3
    const int tid_g = tid & 127;
    const int ng    = (tid >> 5) & 3; // warp-in-group = n group
    const int barid = 1 + grp;
    const int eL    = tid_g >> 4;     // scatter base edge (0..7)
    const int d4    = tid_g & 15;

    Group* G = &s->gr[grp];

    // ldmatrix per-lane offset (bytes) within an A buffer
    const int lrow = ((lane >> 3) & 1) * 8 + (lane & 7);
    const uint32_t laneoff = (uint32_t)(lrow * (A_STRIDE * 4) + (lane >> 4) * 16);
    const uint32_t abuf_addr[2] = { smem_u32(G->A[0]), smem_u32(G->A[1]) };

    // ---- W fragments resident in registers (64 regs/thread) ----
    float2 wreg[16][2];
    #pragma unroll
    for (int ks = 0; ks < 16; ks++) {
        #pragma unroll
        for (int j = 0; j < 2; j++) {
            int n = ng * 16 + j * 8 + g;
            int k = ks * 8 + t;
            wreg[ks][j].x = __uint_as_float(f2tf32_rna(__ldg(W + n * D_R + k)));
            wreg[ks][j].y = __uint_as_float(f2tf32_rna(__ldg(W + n * D_R + k + 4)));
        }
    }
    const float4 bvec = __ldg(reinterpret_cast<const float4*>(bias) + d4);

    const int bid     = blockIdx.x;
    const int n_tiles = (NUM_TILES - bid + GRID - 1) / GRID;

    // ---- prologue: prefetch tile 0 slice + indices ----
    issue_group_tile(G, 0, bid, grp, tid_g, eb, src, dst);
    CP_COMMIT();                    // pending: {A(0)}

    for (int i = 0; i < n_tiles; i++) {
        CP_WAIT0();                 // A(i)+idx(i) resident; xg(i-1) consumed
        GBAR(barid);                // publish A[i&1]+idx; whole group finished
                                    // iter i-1's scatter -> xg/filt reusable

        const int buf = i & 1;

        // ---- issue x-row gathers for THIS tile (own commit group) ----
        {
            #pragma unroll
            for (int r = 0; r < 4; r++) {
                int e_loc = eL + 8 * r;
                int sn = G->sidx[buf][e_loc];
                cp_async16(smem_u32(G->xg + e_loc * XG_STRIDE + d4 * 4),
                           x + (size_t)sn * D_IN + d4 * 4);
            }
        }
        CP_COMMIT();                // pending: {g(i)}

        // ---- prefetch tile i+1 slice (empty group when out of range) ----
        if (i + 1 < n_tiles)
            issue_group_tile(G, (i + 1) & 1, bid + (i + 1) * GRID, grp, tid_g, eb, src, dst);
        CP_COMMIT();                // pending: {g(i), A(i+1)}

        // ---- MMA: warp = 32 edges x 16 n; gathers fly during this ----
        const uint32_t abase = abuf_addr[buf] + laneoff;
        float c[2][2][4];
        #pragma unroll
        for (int m = 0; m < 2; m++)
            #pragma unroll
            for (int j = 0; j < 2; j++)
                { c[m][j][0] = 0.f; c[m][j][1] = 0.f; c[m][j][2] = 0.f; c[m][j][3] = 0.f; }

        #pragma unroll
        for (int ks = 0; ks < 16; ks++) {
            #pragma unroll
            for (int m = 0; m < 2; m++) {
                uint32_t a0, a1, a2, a3;
                ldsm_x4(a0, a1, a2, a3,
                        abase + (uint32_t)(m * 16 * (A_STRIDE * 4) + ks * 32));
                #pragma unroll
                for (int j = 0; j < 2; j++)
                    mma_tf32(c[m][j], a0, a1, a2, a3,
                             __float_as_uint(wreg[ks][j].x),
                             __float_as_uint(wreg[ks][j].y));
            }
        }

        // ---- stage C into group's filt ----
        #pragma unroll
        for (int m = 0; m < 2; m++) {
            float* fr = G->filt + (m * 16 + g) * C_STRIDE + ng * 16;
            #pragma unroll
            for (int j = 0; j < 2; j++) {
                *reinterpret_cast<float2*>(fr + j * 8 + 2 * t) =
                    make_float2(c[m][j][0], c[m][j][1]);
                *reinterpret_cast<float2*>(fr + 8 * C_STRIDE + j * 8 + 2 * t) =
                    make_float2(c[m][j][2], c[m][j][3]);
            }
        }
        GBAR(barid);                // group's filt complete
        CP_WAIT1();                 // g(i) retired (A(i+1) may still fly)

        // ---- scatter: filt (LDS) * xg (LDS), RED to out ----
        #pragma unroll
        for (int rep = 0; rep < 4; rep++) {
            int e_loc = eL + 8 * rep;
            float4 f  = *reinterpret_cast<const float4*>(
                            G->filt + e_loc * C_STRIDE + d4 * 4);
            float4 xv = *reinterpret_cast<const float4*>(
                            G->xg + e_loc * XG_STRIDE + d4 * 4);
            int dn = G->didx[buf][e_loc];
            red_add_v4(out + (size_t)dn * D_IN + d4 * 4,
                       fmaf(f.x, SCALE_FIX, bvec.x) * xv.x,
                       fmaf(f.y, SCALE_FIX, bvec.y) * xv.y,
                       fmaf(f.z, SCALE_FIX, bvec.z) * xv.z,
                       fmaf(f.w, SCALE_FIX, bvec.w) * xv.w);
        }
        // Next iteration's top GBAR (after CP_WAIT0) orders these xg/filt/idx
        // reads before their overwrites (gather(i+1) / staging / A(i+2)).
    }
}

extern "C" void kernel_launch(void* const* d_in, const int* in_sizes, int n_in,
                              void* d_out, int out_size) {
    const float* x    = (const float*)d_in[0];
    const float* eb   = (const float*)d_in[1];
    const int*   src  = (const int*)d_in[2];
    const int*   dst  = (const int*)d_in[3];
    const float* W    = (const float*)d_in[4];
    const float* bias = (const float*)d_in[5];
    float* out = (float*)d_out;

    int n4 = out_size / 4;
    zero_out_kernel<<<(n4 + 255) / 256, 256>>>((float4*)out, n4);

    cudaFuncSetAttribute(fused_tf32_xg,
                         cudaFuncAttributeMaxDynamicSharedMemorySize,
                         (int)sizeof(Smem));
    fused_tf32_xg<<<GRID, NTHREADS, sizeof(Smem)>>>(x, eb, src, dst, W, bias, out);
}